// round 2
// baseline (speedup 1.0000x reference)
#include <cuda_runtime.h>
#include <math.h>

// ---------------------------------------------------------------------------
// MultiHeadAttention: B=4, L=2048, C=512, single head, fp32.
//   q = query@Wq+bq; k = key@Wk+bk; v = value@Wv+bv
//   att = softmax(q k^T / sqrt(C)); ctx = att v; out = ctx@Wo+bo
// Round 0: staged fp32 SGEMM baseline (128x128x16 tiles, 8x8 micro-tile).
// ---------------------------------------------------------------------------

#define Bv   4
#define Lv   2048
#define Cv   512
#define Mfull (Bv * Lv)          // 8192

// scratch (static device arrays: allocation-free)
__device__ float g_q  [Bv * Lv * Cv];               // 16 MB
__device__ float g_k  [Bv * Lv * Cv];               // 16 MB
__device__ float g_v  [Bv * Lv * Cv];               // 16 MB
__device__ float g_att[(size_t)Bv * Lv * Lv];       // 64 MB
__device__ float g_ctx[Bv * Lv * Cv];               // 16 MB

#define BM 128
#define BN 128
#define BK 16
#define TM 8
#define TN 8
// 256 threads, each computes an 8x8 micro-tile of the 128x128 block tile.

// C[b] = alpha * A[b] @ op(B[b]) (+ bias), all row-major fp32.
//   TRANSB=false: op(B)(k,n) = B[k*ldb + n]
//   TRANSB=true : op(B)(k,n) = B[n*ldb + k]   (i.e. C = A @ B^T)
// M,N multiples of 128; K multiple of 16. No bounds checks (shapes guarantee).
template <bool TRANSB, bool BIAS>
__global__ __launch_bounds__(256, 2)
void gemm_kernel(const float* __restrict__ A, const float* __restrict__ B,
                 const float* __restrict__ bias, float* __restrict__ C,
                 int M, int N, int K, int lda, int ldb, int ldc,
                 long strideA, long strideB, long strideC, float alpha)
{
    __shared__ float As[BK][BM];   // stored k-major for broadcast reads
    __shared__ float Bs[BK][BN];

    const int bz = blockIdx.z;
    A += (long)bz * strideA;
    B += (long)bz * strideB;
    C += (long)bz * strideC;

    const int bm  = blockIdx.y * BM;
    const int bn  = blockIdx.x * BN;
    const int tid = threadIdx.x;

    const int tr = tid >> 4;   // 0..15 (row group)
    const int tc = tid & 15;   // 0..15 (col group)

    float acc[TM][TN];
    #pragma unroll
    for (int i = 0; i < TM; i++)
        #pragma unroll
        for (int j = 0; j < TN; j++) acc[i][j] = 0.0f;

    for (int k0 = 0; k0 < K; k0 += BK) {
        // ---- load A tile: BM x BK (512 float4, 2 per thread), transpose to As[k][m]
        #pragma unroll
        for (int i = 0; i < 2; i++) {
            int idx = tid + i * 256;           // float4 index
            int row = idx >> 2;                // 0..127
            int col = (idx & 3) << 2;          // 0,4,8,12
            float4 va = *reinterpret_cast<const float4*>(
                A + (long)(bm + row) * lda + (k0 + col));
            As[col + 0][row] = va.x;
            As[col + 1][row] = va.y;
            As[col + 2][row] = va.z;
            As[col + 3][row] = va.w;
        }
        // ---- load B tile: BK x BN into Bs[k][n]
        if (!TRANSB) {
            #pragma unroll
            for (int i = 0; i < 2; i++) {
                int idx = tid + i * 256;
                int row = idx >> 5;            // 0..15 (k)
                int col = (idx & 31) << 2;     // 0..124
                float4 vb = *reinterpret_cast<const float4*>(
                    B + (long)(k0 + row) * ldb + (bn + col));
                *reinterpret_cast<float4*>(&Bs[row][col]) = vb;
            }
        } else {
            #pragma unroll
            for (int i = 0; i < 2; i++) {
                int idx = tid + i * 256;
                int n  = idx >> 2;             // 0..127
                int kk = (idx & 3) << 2;       // 0,4,8,12
                float4 vb = *reinterpret_cast<const float4*>(
                    B + (long)(bn + n) * ldb + (k0 + kk));
                Bs[kk + 0][n] = vb.x;
                Bs[kk + 1][n] = vb.y;
                Bs[kk + 2][n] = vb.z;
                Bs[kk + 3][n] = vb.w;
            }
        }
        __syncthreads();

        // ---- compute
        #pragma unroll
        for (int kk = 0; kk < BK; kk++) {
            float ar[TM], br[TN];
            #pragma unroll
            for (int i = 0; i < TM; i++) ar[i] = As[kk][tr * TM + i];
            #pragma unroll
            for (int j = 0; j < TN; j++) br[j] = Bs[kk][tc * TN + j];
            #pragma unroll
            for (int i = 0; i < TM; i++)
                #pragma unroll
                for (int j = 0; j < TN; j++)
                    acc[i][j] += ar[i] * br[j];
        }
        __syncthreads();
    }

    // ---- epilogue
    #pragma unroll
    for (int i = 0; i < TM; i++) {
        int row = bm + tr * TM + i;
        #pragma unroll
        for (int j = 0; j < TN; j += 4) {
            int col = bn + tc * TN + j;
            float4 v;
            v.x = acc[i][j + 0] * alpha;
            v.y = acc[i][j + 1] * alpha;
            v.z = acc[i][j + 2] * alpha;
            v.w = acc[i][j + 3] * alpha;
            if (BIAS) {
                v.x += bias[col + 0];
                v.y += bias[col + 1];
                v.z += bias[col + 2];
                v.w += bias[col + 3];
            }
            *reinterpret_cast<float4*>(C + (long)row * ldc + col) = v;
        }
    }
}

// Row-wise softmax over the last dim (L=2048), in place. One block per row.
__global__ __launch_bounds__(256)
void softmax_kernel(float* __restrict__ att)
{
    const int L = Lv;
    float* p = att + (size_t)blockIdx.x * L;
    const int tid  = threadIdx.x;
    const int lane = tid & 31;
    const int warp = tid >> 5;

    __shared__ float red[8];

    float v[8];
    float m = -1e30f;
    #pragma unroll
    for (int i = 0; i < 8; i++) {
        v[i] = p[i * 256 + tid];
        m = fmaxf(m, v[i]);
    }
    #pragma unroll
    for (int o = 16; o > 0; o >>= 1)
        m = fmaxf(m, __shfl_xor_sync(0xFFFFFFFFu, m, o));
    if (lane == 0) red[warp] = m;
    __syncthreads();
    m = red[0];
    #pragma unroll
    for (int i = 1; i < 8; i++) m = fmaxf(m, red[i]);
    __syncthreads();

    float s = 0.0f;
    #pragma unroll
    for (int i = 0; i < 8; i++) {
        v[i] = expf(v[i] - m);
        s += v[i];
    }
    #pragma unroll
    for (int o = 16; o > 0; o >>= 1)
        s += __shfl_xor_sync(0xFFFFFFFFu, s, o);
    if (lane == 0) red[warp] = s;
    __syncthreads();
    s = red[0];
    #pragma unroll
    for (int i = 1; i < 8; i++) s += red[i];

    float inv = 1.0f / s;
    #pragma unroll
    for (int i = 0; i < 8; i++)
        p[i * 256 + tid] = v[i] * inv;
}

extern "C" void kernel_launch(void* const* d_in, const int* in_sizes, int n_in,
                              void* d_out, int out_size)
{
    const float* query = (const float*)d_in[0];
    const float* key   = (const float*)d_in[1];
    const float* value = (const float*)d_in[2];
    const float* Wq    = (const float*)d_in[3];
    const float* bq    = (const float*)d_in[4];
    const float* Wk    = (const float*)d_in[5];
    const float* bk    = (const float*)d_in[6];
    const float* Wv    = (const float*)d_in[7];
    const float* bv    = (const float*)d_in[8];
    const float* Wo    = (const float*)d_in[9];
    const float* bo    = (const float*)d_in[10];
    float* out = (float*)d_out;

    void *pq, *pk, *pv, *patt, *pctx;
    cudaGetSymbolAddress(&pq,   g_q);
    cudaGetSymbolAddress(&pk,   g_k);
    cudaGetSymbolAddress(&pv,   g_v);
    cudaGetSymbolAddress(&patt, g_att);
    cudaGetSymbolAddress(&pctx, g_ctx);
    float* q   = (float*)pq;
    float* k   = (float*)pk;
    float* v   = (float*)pv;
    float* att = (float*)patt;
    float* ctx = (float*)pctx;

    const float scale = 1.0f / sqrtf((float)Cv);
    dim3 blk(256);

    // 1) projections: [8192,512] = [8192,512] @ [512,512] + bias
    dim3 gproj(Cv / BN, Mfull / BM, 1);
    gemm_kernel<false, true><<<gproj, blk>>>(query, Wq, bq, q,
        Mfull, Cv, Cv, Cv, Cv, Cv, 0, 0, 0, 1.0f);
    gemm_kernel<false, true><<<gproj, blk>>>(key,   Wk, bk, k,
        Mfull, Cv, Cv, Cv, Cv, Cv, 0, 0, 0, 1.0f);
    gemm_kernel<false, true><<<gproj, blk>>>(value, Wv, bv, v,
        Mfull, Cv, Cv, Cv, Cv, Cv, 0, 0, 0, 1.0f);

    // 2) scores: att[b] = scale * q[b] @ k[b]^T   [2048,2048], K=512
    dim3 gsc(Lv / BN, Lv / BM, Bv);
    gemm_kernel<true, false><<<gsc, blk>>>(q, k, nullptr, att,
        Lv, Lv, Cv, Cv, Cv, Lv,
        (long)Lv * Cv, (long)Lv * Cv, (long)Lv * Lv, scale);

    // 3) softmax rows (B*L rows of length L)
    softmax_kernel<<<Mfull, blk>>>(att);

    // 4) ctx[b] = att[b] @ v[b]   [2048,512], K=2048
    dim3 gav(Cv / BN, Lv / BM, Bv);
    gemm_kernel<false, false><<<gav, blk>>>(att, v, nullptr, ctx,
        Lv, Cv, Lv, Lv, Cv, Cv,
        (long)Lv * Lv, (long)Lv * Cv, (long)Lv * Cv, 1.0f);

    // 5) output projection: out = ctx @ Wo + bo
    gemm_kernel<false, true><<<gproj, blk>>>(ctx, Wo, bo, out,
        Mfull, Cv, Cv, Cv, Cv, Cv, 0, 0, 0, 1.0f);
}

// round 5
// speedup vs baseline: 1.9684x; 1.9684x over previous
#include <cuda_runtime.h>
#include <cuda_bf16.h>
#include <math.h>
#include <stdint.h>

// ---------------------------------------------------------------------------
// MultiHeadAttention B=4, L=2048, C=512 — bf16x3 via mma.sync (HMMA path).
//   fp32 X split: hi = bf16(X), lo = bf16(X - hi)
//   A@B ≈ Ahi@Bhi + Ahi@Blo + Alo@Bhi  (fp32 accumulate in registers)
// All GEMMs: D[M,N] = A[M,K] @ B[N,K]^T  (both operands K-major).
// tcgen05 is unavailable (harness PTX target is sm_103 without 'a');
// ldmatrix + mma.sync.m16n8k16 compile for plain sm_103.
// ---------------------------------------------------------------------------

#define Bv   4
#define Lv   2048
#define Cv   512
#define Mfull (Bv * Lv)          // 8192

typedef __nv_bfloat16 bf16;

// ---------------- static scratch (allocation-free) ----------------
__device__ bf16 g_xq_hi[Mfull * Cv], g_xq_lo[Mfull * Cv];
__device__ bf16 g_xk_hi[Mfull * Cv], g_xk_lo[Mfull * Cv];
__device__ bf16 g_xv_hi[Mfull * Cv], g_xv_lo[Mfull * Cv];
__device__ bf16 g_wqt_hi[Cv * Cv], g_wqt_lo[Cv * Cv];
__device__ bf16 g_wkt_hi[Cv * Cv], g_wkt_lo[Cv * Cv];
__device__ bf16 g_wvt_hi[Cv * Cv], g_wvt_lo[Cv * Cv];
__device__ bf16 g_wot_hi[Cv * Cv], g_wot_lo[Cv * Cv];
__device__ bf16 g_q_hi [Mfull * Cv], g_q_lo [Mfull * Cv];
__device__ bf16 g_k_hi [Mfull * Cv], g_k_lo [Mfull * Cv];
__device__ bf16 g_vt_hi[Mfull * Cv], g_vt_lo[Mfull * Cv];   // [B][C][L]
__device__ float g_att[(size_t)Bv * Lv * Lv];                // 64 MB
__device__ bf16 g_att_hi[(size_t)Bv * Lv * Lv], g_att_lo[(size_t)Bv * Lv * Lv];
__device__ bf16 g_ctx_hi[Mfull * Cv], g_ctx_lo[Mfull * Cv];

__device__ __forceinline__ uint32_t smem_u32(const void* p) {
    uint32_t a;
    asm("{ .reg .u64 t; cvta.to.shared.u64 t, %1; cvt.u32.u64 %0, t; }"
        : "=r"(a) : "l"(p));
    return a;
}

__device__ __forceinline__ void ldmatrix_x4(uint32_t* r, uint32_t addr) {
    asm volatile("ldmatrix.sync.aligned.m8n8.x4.shared.b16 {%0,%1,%2,%3}, [%4];"
                 : "=r"(r[0]), "=r"(r[1]), "=r"(r[2]), "=r"(r[3]) : "r"(addr));
}

__device__ __forceinline__ void mma_bf16(float* d, const uint32_t* a,
                                         uint32_t b0, uint32_t b1) {
    asm volatile(
        "mma.sync.aligned.m16n8k16.row.col.f32.bf16.bf16.f32 "
        "{%0,%1,%2,%3}, {%4,%5,%6,%7}, {%8,%9}, {%0,%1,%2,%3};"
        : "+f"(d[0]), "+f"(d[1]), "+f"(d[2]), "+f"(d[3])
        : "r"(a[0]), "r"(a[1]), "r"(a[2]), "r"(a[3]), "r"(b0), "r"(b1));
}

// ---------------------------------------------------------------------------
// GEMM: 128x128 CTA tile, 256 threads. Warp grid 2(M) x 4(N); warp tile 64x32.
// K-chunk = 32. SMEM row: hi[32] | lo[32] bf16, pitch 72 (row+16B pad,
// conflict-free ldmatrix).
// OUT_MODE: 0 = fp32 row-major, 1 = bf16 hi/lo row-major, 2 = bf16 hi/lo transp.
// ---------------------------------------------------------------------------
#define BKC 32
#define LDP 72        // smem row pitch in bf16

__device__ __forceinline__ void load_tile(
    const bf16* __restrict__ hi, const bf16* __restrict__ lo,
    int row0, int ldx, int k0, bf16* sm, int tid)
{
    #pragma unroll
    for (int i = 0; i < 4; i++) {
        int idx  = tid + i * 256;        // 0..1023 uint4 units
        int r    = idx >> 3;             // 0..127 tile row
        int half = (idx >> 2) & 1;       // 0=hi, 1=lo
        int s    = idx & 3;              // 16B segment
        const bf16* src = half ? lo : hi;
        uint4 v = *(reinterpret_cast<const uint4*>(
                        src + (size_t)(row0 + r) * ldx + k0) + s);
        *reinterpret_cast<uint4*>(sm + r * LDP + half * 32 + s * 8) = v;
    }
}

template <int OUT_MODE, bool BIAS>
__global__ __launch_bounds__(256, 2)
void mma_gemm(const bf16* __restrict__ Ahi, const bf16* __restrict__ Alo,
              const bf16* __restrict__ Bhi, const bf16* __restrict__ Blo,
              const float* __restrict__ bias,
              float* __restrict__ Cf, bf16* __restrict__ Chi, bf16* __restrict__ Clo,
              int K, int lda, int ldb, int ldc,
              long strA, long strB, long strC, float alpha)
{
    __shared__ __align__(16) bf16 sA[128 * LDP];
    __shared__ __align__(16) bf16 sB[128 * LDP];

    const int bz = blockIdx.z;
    Ahi += (long)bz * strA;  Alo += (long)bz * strA;
    Bhi += (long)bz * strB;  Blo += (long)bz * strB;
    if (OUT_MODE == 0) Cf += (long)bz * strC;
    else { Chi += (long)bz * strC; Clo += (long)bz * strC; }

    const int bm   = blockIdx.y * 128;
    const int bn   = blockIdx.x * 128;
    const int tid  = threadIdx.x;
    const int wid  = tid >> 5;
    const int lane = tid & 31;
    const int wm   = (wid & 1) * 64;     // warp M offset in tile
    const int wn   = (wid >> 1) * 32;    // warp N offset in tile

    const uint32_t sa_base = smem_u32(sA);
    const uint32_t sb_base = smem_u32(sB);
    // ldmatrix lane addressing: row = lane&15, col-half = lane>>4 (8 elems)
    const int lrow = lane & 15;
    const int lcol = (lane >> 4) * 8;

    float acc[4][4][4];
    #pragma unroll
    for (int i = 0; i < 4; i++)
        #pragma unroll
        for (int j = 0; j < 4; j++)
            #pragma unroll
            for (int r = 0; r < 4; r++) acc[i][j][r] = 0.0f;

    for (int k0 = 0; k0 < K; k0 += BKC) {
        load_tile(Ahi, Alo, bm, lda, k0, sA, tid);
        load_tile(Bhi, Blo, bn, ldb, k0, sB, tid);
        __syncthreads();

        // 3 terms: (Ahi,Bhi), (Ahi,Blo), (Alo,Bhi); halves at col 0 / 32
        #pragma unroll
        for (int term = 0; term < 3; term++) {
            const int ka = (term == 2) ? 32 : 0;   // A half offset
            const int kb = (term == 1) ? 32 : 0;   // B half offset
            #pragma unroll
            for (int t = 0; t < 2; t++) {          // two k16 steps
                const int ac = ka + t * 16 + lcol;
                const int bc = kb + t * 16 + lcol;
                uint32_t afr[4][4];
                #pragma unroll
                for (int mt = 0; mt < 4; mt++) {
                    uint32_t addr = sa_base +
                        ((wm + mt * 16 + lrow) * LDP + ac) * 2;
                    ldmatrix_x4(afr[mt], addr);
                }
                uint32_t bfr[2][4];
                #pragma unroll
                for (int nb = 0; nb < 2; nb++) {
                    uint32_t addr = sb_base +
                        ((bn >= 0 ? (wn + nb * 16 + lrow) : 0) * LDP + bc) * 2;
                    ldmatrix_x4(bfr[nb], addr);
                }
                #pragma unroll
                for (int mt = 0; mt < 4; mt++)
                    #pragma unroll
                    for (int nt = 0; nt < 4; nt++) {
                        const int nb  = nt >> 1;
                        const int sel = nt & 1;
                        mma_bf16(acc[mt][nt], afr[mt],
                                 bfr[nb][sel], bfr[nb][sel + 2]);
                    }
            }
        }
        __syncthreads();
    }

    // ---- epilogue: fragment (mt,nt) reg r -> row = wm+mt*16+(lane>>2)+8*(r>>1),
    //                                          col = wn+nt*8+(lane&3)*2+(r&1)
    const int er = lane >> 2;          // 0..7
    const int ec = (lane & 3) * 2;     // 0,2,4,6
    #pragma unroll
    for (int mt = 0; mt < 4; mt++) {
        #pragma unroll
        for (int half = 0; half < 2; half++) {   // r pair: {0,1} or {2,3}
            const int row = bm + wm + mt * 16 + er + half * 8;
            #pragma unroll
            for (int nt = 0; nt < 4; nt++) {
                const int col = bn + wn + nt * 8 + ec;
                float f0 = acc[mt][nt][half * 2 + 0] * alpha;
                float f1 = acc[mt][nt][half * 2 + 1] * alpha;
                if (BIAS) {
                    f0 += __ldg(&bias[col]);
                    f1 += __ldg(&bias[col + 1]);
                }
                if (OUT_MODE == 0) {
                    *reinterpret_cast<float2*>(Cf + (size_t)row * ldc + col) =
                        make_float2(f0, f1);
                } else if (OUT_MODE == 1) {
                    bf16 h0 = __float2bfloat16(f0);
                    bf16 h1 = __float2bfloat16(f1);
                    bf16 l0 = __float2bfloat16(f0 - __bfloat162float(h0));
                    bf16 l1 = __float2bfloat16(f1 - __bfloat162float(h1));
                    *reinterpret_cast<__nv_bfloat162*>(
                        Chi + (size_t)row * ldc + col) = __nv_bfloat162(h0, h1);
                    *reinterpret_cast<__nv_bfloat162*>(
                        Clo + (size_t)row * ldc + col) = __nv_bfloat162(l0, l1);
                } else {  // transposed store
                    bf16 h0 = __float2bfloat16(f0);
                    bf16 h1 = __float2bfloat16(f1);
                    bf16 l0 = __float2bfloat16(f0 - __bfloat162float(h0));
                    bf16 l1 = __float2bfloat16(f1 - __bfloat162float(h1));
                    size_t o0 = (size_t)col * ldc + row;
                    size_t o1 = (size_t)(col + 1) * ldc + row;
                    Chi[o0] = h0;  Clo[o0] = l0;
                    Chi[o1] = h1;  Clo[o1] = l1;
                }
            }
        }
    }
}

// ---------------------------------------------------------------------------
// fp32 -> (hi, lo) bf16 split, vectorized float4
// ---------------------------------------------------------------------------
__global__ __launch_bounds__(256)
void split_kernel(const float* __restrict__ x, bf16* __restrict__ hi,
                  bf16* __restrict__ lo, int n4)
{
    int i = blockIdx.x * 256 + threadIdx.x;
    if (i >= n4) return;
    float4 v = reinterpret_cast<const float4*>(x)[i];
    bf16 h0 = __float2bfloat16(v.x), h1 = __float2bfloat16(v.y);
    bf16 h2 = __float2bfloat16(v.z), h3 = __float2bfloat16(v.w);
    bf16 l0 = __float2bfloat16(v.x - __bfloat162float(h0));
    bf16 l1 = __float2bfloat16(v.y - __bfloat162float(h1));
    bf16 l2 = __float2bfloat16(v.z - __bfloat162float(h2));
    bf16 l3 = __float2bfloat16(v.w - __bfloat162float(h3));
    reinterpret_cast<__nv_bfloat162*>(hi)[i * 2]     = __nv_bfloat162(h0, h1);
    reinterpret_cast<__nv_bfloat162*>(hi)[i * 2 + 1] = __nv_bfloat162(h2, h3);
    reinterpret_cast<__nv_bfloat162*>(lo)[i * 2]     = __nv_bfloat162(l0, l1);
    reinterpret_cast<__nv_bfloat162*>(lo)[i * 2 + 1] = __nv_bfloat162(l2, l3);
}

// W [C,C] row-major -> WT hi/lo [C,C] (WT[n][k] = W[k][n])
__global__ __launch_bounds__(256)
void tsplit_kernel(const float* __restrict__ W, bf16* __restrict__ hi,
                   bf16* __restrict__ lo)
{
    int idx = blockIdx.x * 256 + threadIdx.x;   // [n][k]
    int n = idx >> 9, k = idx & 511;
    float x = __ldg(&W[k * Cv + n]);
    bf16 h = __float2bfloat16(x);
    hi[idx] = h;
    lo[idx] = __float2bfloat16(x - __bfloat162float(h));
}

// softmax over L=2048 (fp32 in) -> hi/lo bf16 out
__global__ __launch_bounds__(256)
void softmax_split_kernel(const float* __restrict__ att,
                          bf16* __restrict__ ahi, bf16* __restrict__ alo)
{
    const size_t base = (size_t)blockIdx.x * Lv;
    const float* p = att + base;
    const int tid = threadIdx.x, lane = tid & 31, warp = tid >> 5;
    __shared__ float red[8];

    float v[8];
    float m = -1e30f;
    #pragma unroll
    for (int i = 0; i < 8; i++) { v[i] = p[i * 256 + tid]; m = fmaxf(m, v[i]); }
    #pragma unroll
    for (int o = 16; o > 0; o >>= 1) m = fmaxf(m, __shfl_xor_sync(~0u, m, o));
    if (lane == 0) red[warp] = m;
    __syncthreads();
    m = red[0];
    #pragma unroll
    for (int i = 1; i < 8; i++) m = fmaxf(m, red[i]);
    __syncthreads();

    float s = 0.0f;
    #pragma unroll
    for (int i = 0; i < 8; i++) { v[i] = expf(v[i] - m); s += v[i]; }
    #pragma unroll
    for (int o = 16; o > 0; o >>= 1) s += __shfl_xor_sync(~0u, s, o);
    if (lane == 0) red[warp] = s;
    __syncthreads();
    s = red[0];
    #pragma unroll
    for (int i = 1; i < 8; i++) s += red[i];

    float inv = 1.0f / s;
    #pragma unroll
    for (int i = 0; i < 8; i++) {
        float w = v[i] * inv;
        bf16 h = __float2bfloat16(w);
        ahi[base + i * 256 + tid] = h;
        alo[base + i * 256 + tid] = __float2bfloat16(w - __bfloat162float(h));
    }
}

// ---------------------------------------------------------------------------
extern "C" void kernel_launch(void* const* d_in, const int* in_sizes, int n_in,
                              void* d_out, int out_size)
{
    const float* query = (const float*)d_in[0];
    const float* key   = (const float*)d_in[1];
    const float* value = (const float*)d_in[2];
    const float* Wq    = (const float*)d_in[3];
    const float* bq    = (const float*)d_in[4];
    const float* Wk    = (const float*)d_in[5];
    const float* bk    = (const float*)d_in[6];
    const float* Wv    = (const float*)d_in[7];
    const float* bv    = (const float*)d_in[8];
    const float* Wo    = (const float*)d_in[9];
    const float* bo    = (const float*)d_in[10];
    float* out = (float*)d_out;

    #define SYM(T, v, s) T* v; { void* _p; cudaGetSymbolAddress(&_p, s); v = (T*)_p; }
    SYM(bf16, xq_hi, g_xq_hi)  SYM(bf16, xq_lo, g_xq_lo)
    SYM(bf16, xk_hi, g_xk_hi)  SYM(bf16, xk_lo, g_xk_lo)
    SYM(bf16, xv_hi, g_xv_hi)  SYM(bf16, xv_lo, g_xv_lo)
    SYM(bf16, wqt_hi, g_wqt_hi) SYM(bf16, wqt_lo, g_wqt_lo)
    SYM(bf16, wkt_hi, g_wkt_hi) SYM(bf16, wkt_lo, g_wkt_lo)
    SYM(bf16, wvt_hi, g_wvt_hi) SYM(bf16, wvt_lo, g_wvt_lo)
    SYM(bf16, wot_hi, g_wot_hi) SYM(bf16, wot_lo, g_wot_lo)
    SYM(bf16, q_hi, g_q_hi)    SYM(bf16, q_lo, g_q_lo)
    SYM(bf16, k_hi, g_k_hi)    SYM(bf16, k_lo, g_k_lo)
    SYM(bf16, vt_hi, g_vt_hi)  SYM(bf16, vt_lo, g_vt_lo)
    SYM(float, att, g_att)
    SYM(bf16, att_hi, g_att_hi) SYM(bf16, att_lo, g_att_lo)
    SYM(bf16, ctx_hi, g_ctx_hi) SYM(bf16, ctx_lo, g_ctx_lo)
    #undef SYM

    const float scale = 1.0f / sqrtf((float)Cv);
    const int n4 = Mfull * Cv / 4;
    dim3 blk(256);

    // 0) split inputs and weights to bf16 hi/lo
    split_kernel<<<n4 / 256, blk>>>(query, xq_hi, xq_lo, n4);
    split_kernel<<<n4 / 256, blk>>>(key,   xk_hi, xk_lo, n4);
    split_kernel<<<n4 / 256, blk>>>(value, xv_hi, xv_lo, n4);
    tsplit_kernel<<<Cv * Cv / 256, blk>>>(Wq, wqt_hi, wqt_lo);
    tsplit_kernel<<<Cv * Cv / 256, blk>>>(Wk, wkt_hi, wkt_lo);
    tsplit_kernel<<<Cv * Cv / 256, blk>>>(Wv, wvt_hi, wvt_lo);
    tsplit_kernel<<<Cv * Cv / 256, blk>>>(Wo, wot_hi, wot_lo);

    const long sIO  = (long)Lv * Cv;
    const long sAtt = (long)Lv * Lv;

    // 1) projections (weights strB = 0)
    dim3 gproj(Cv / 128, Lv / 128, Bv);  // (4,16,4)
    mma_gemm<1, true><<<gproj, blk>>>(xq_hi, xq_lo, wqt_hi, wqt_lo, bq,
        nullptr, q_hi, q_lo, Cv, Cv, Cv, Cv, sIO, 0, sIO, 1.0f);
    mma_gemm<1, true><<<gproj, blk>>>(xk_hi, xk_lo, wkt_hi, wkt_lo, bk,
        nullptr, k_hi, k_lo, Cv, Cv, Cv, Cv, sIO, 0, sIO, 1.0f);
    // V projection writes V^T [C, L] per batch (ldc = L)
    mma_gemm<2, true><<<gproj, blk>>>(xv_hi, xv_lo, wvt_hi, wvt_lo, bv,
        nullptr, vt_hi, vt_lo, Cv, Cv, Cv, Lv, sIO, 0, sIO, 1.0f);

    // 2) scores: att[b] = scale * q[b] @ k[b]^T (fp32 out)
    dim3 gsc(Lv / 128, Lv / 128, Bv);    // (16,16,4)
    mma_gemm<0, false><<<gsc, blk>>>(q_hi, q_lo, k_hi, k_lo, nullptr,
        att, nullptr, nullptr, Cv, Cv, Cv, Lv, sIO, sIO, sAtt, scale);

    // 3) softmax + bf16 split
    softmax_split_kernel<<<Mfull, blk>>>(att, att_hi, att_lo);

    // 4) ctx[b] = att[b] @ v[b]  (B = V^T, K-major)
    dim3 gav(Cv / 128, Lv / 128, Bv);    // (4,16,4)
    mma_gemm<1, false><<<gav, blk>>>(att_hi, att_lo, vt_hi, vt_lo, nullptr,
        nullptr, ctx_hi, ctx_lo, Lv, Lv, Lv, Cv, sAtt, sIO, sIO, 1.0f);

    // 5) out = ctx @ Wo + bo (fp32 to d_out)
    mma_gemm<0, true><<<gproj, blk>>>(ctx_hi, ctx_lo, wot_hi, wot_lo, bo,
        out, nullptr, nullptr, Cv, Cv, Cv, Cv, sIO, 0, sIO, 1.0f);
}

// round 6
// speedup vs baseline: 2.1071x; 1.0704x over previous
#include <cuda_runtime.h>
#include <cuda_bf16.h>
#include <math.h>
#include <stdint.h>

// ---------------------------------------------------------------------------
// MultiHeadAttention B=4, L=2048, C=512 — bf16x3 via mma.sync (HMMA path).
//   fp32 X split: hi = bf16(X), lo = bf16(X - hi)
//   A@B ≈ Ahi@Bhi + Ahi@Blo + Alo@Bhi  (fp32 accumulate in registers)
// All GEMMs: D[M,N] = A[M,K] @ B[N,K]^T  (both operands K-major).
// R5: cp.async double-buffered mainloop + ldmatrix fragment reuse.
// ---------------------------------------------------------------------------

#define Bv   4
#define Lv   2048
#define Cv   512
#define Mfull (Bv * Lv)          // 8192

typedef __nv_bfloat16 bf16;

// ---------------- static scratch (allocation-free) ----------------
__device__ bf16 g_xq_hi[Mfull * Cv], g_xq_lo[Mfull * Cv];
__device__ bf16 g_xk_hi[Mfull * Cv], g_xk_lo[Mfull * Cv];
__device__ bf16 g_xv_hi[Mfull * Cv], g_xv_lo[Mfull * Cv];
__device__ bf16 g_wqt_hi[Cv * Cv], g_wqt_lo[Cv * Cv];
__device__ bf16 g_wkt_hi[Cv * Cv], g_wkt_lo[Cv * Cv];
__device__ bf16 g_wvt_hi[Cv * Cv], g_wvt_lo[Cv * Cv];
__device__ bf16 g_wot_hi[Cv * Cv], g_wot_lo[Cv * Cv];
__device__ bf16 g_q_hi [Mfull * Cv], g_q_lo [Mfull * Cv];
__device__ bf16 g_k_hi [Mfull * Cv], g_k_lo [Mfull * Cv];
__device__ bf16 g_vt_hi[Mfull * Cv], g_vt_lo[Mfull * Cv];   // [B][C][L]
__device__ float g_att[(size_t)Bv * Lv * Lv];                // 64 MB
__device__ bf16 g_att_hi[(size_t)Bv * Lv * Lv], g_att_lo[(size_t)Bv * Lv * Lv];
__device__ bf16 g_ctx_hi[Mfull * Cv], g_ctx_lo[Mfull * Cv];

__device__ __forceinline__ uint32_t smem_u32(const void* p) {
    uint32_t a;
    asm("{ .reg .u64 t; cvta.to.shared.u64 t, %1; cvt.u32.u64 %0, t; }"
        : "=r"(a) : "l"(p));
    return a;
}
__device__ __forceinline__ void ldmatrix_x4(uint32_t* r, uint32_t addr) {
    asm volatile("ldmatrix.sync.aligned.m8n8.x4.shared.b16 {%0,%1,%2,%3}, [%4];"
                 : "=r"(r[0]), "=r"(r[1]), "=r"(r[2]), "=r"(r[3]) : "r"(addr));
}
__device__ __forceinline__ void mma_bf16(float* d, const uint32_t* a,
                                         uint32_t b0, uint32_t b1) {
    asm volatile(
        "mma.sync.aligned.m16n8k16.row.col.f32.bf16.bf16.f32 "
        "{%0,%1,%2,%3}, {%4,%5,%6,%7}, {%8,%9}, {%0,%1,%2,%3};"
        : "+f"(d[0]), "+f"(d[1]), "+f"(d[2]), "+f"(d[3])
        : "r"(a[0]), "r"(a[1]), "r"(a[2]), "r"(a[3]), "r"(b0), "r"(b1));
}
__device__ __forceinline__ void cp16(uint32_t dst, const void* src) {
    asm volatile("cp.async.cg.shared.global [%0], [%1], 16;"
                 :: "r"(dst), "l"(src));
}
#define CP_COMMIT()  asm volatile("cp.async.commit_group;" ::: "memory")
#define CP_WAIT1()   asm volatile("cp.async.wait_group 1;" ::: "memory")

// ---------------------------------------------------------------------------
// GEMM: 128x128 CTA tile, 256 threads. Warp grid 2(M) x 4(N); warp tile 64x32.
// K-chunk = 32. SMEM row: hi[32] | lo[32] bf16, pitch 72 bf16 (conflict-free).
// Double-buffered via cp.async. Dynamic smem = 4 * 128*72*2 = 73728 B.
// OUT_MODE: 0 = fp32 row-major, 1 = bf16 hi/lo row-major, 2 = bf16 hi/lo transp.
// ---------------------------------------------------------------------------
#define BKC 32
#define LDP 72                         // smem row pitch in bf16
#define TILE_ELEMS (128 * LDP)         // per operand per buffer
#define SMEM_BYTES (4 * TILE_ELEMS * 2)

__device__ __forceinline__ void load_tile_cp(
    const bf16* __restrict__ hi, const bf16* __restrict__ lo,
    int row0, int ldx, int k0, uint32_t sm, int tid)
{
    #pragma unroll
    for (int i = 0; i < 4; i++) {
        int idx  = tid + i * 256;        // 0..1023 (16B units)
        int r    = idx >> 3;             // tile row 0..127
        int half = (idx >> 2) & 1;       // 0=hi, 1=lo
        int s    = idx & 3;              // 16B segment
        const bf16* src = (half ? lo : hi)
                        + (size_t)(row0 + r) * ldx + k0 + s * 8;
        cp16(sm + (uint32_t)(r * LDP + half * 32 + s * 8) * 2, src);
    }
}

template <int OUT_MODE, bool BIAS>
__global__ __launch_bounds__(256, 2)
void mma_gemm(const bf16* __restrict__ Ahi, const bf16* __restrict__ Alo,
              const bf16* __restrict__ Bhi, const bf16* __restrict__ Blo,
              const float* __restrict__ bias,
              float* __restrict__ Cf, bf16* __restrict__ Chi, bf16* __restrict__ Clo,
              int K, int lda, int ldb, int ldc,
              long strA, long strB, long strC, float alpha)
{
    extern __shared__ __align__(16) bf16 smem[];
    // layout: [bufA0][bufB0][bufA1][bufB1]
    const uint32_t s_base = smem_u32(smem);
    const uint32_t sA[2] = { s_base,
                             s_base + 2u * TILE_ELEMS * 2 };
    const uint32_t sB[2] = { s_base + 1u * TILE_ELEMS * 2,
                             s_base + 3u * TILE_ELEMS * 2 };

    const int bz = blockIdx.z;
    Ahi += (long)bz * strA;  Alo += (long)bz * strA;
    Bhi += (long)bz * strB;  Blo += (long)bz * strB;
    if (OUT_MODE == 0) Cf += (long)bz * strC;
    else { Chi += (long)bz * strC; Clo += (long)bz * strC; }

    const int bm   = blockIdx.y * 128;
    const int bn   = blockIdx.x * 128;
    const int tid  = threadIdx.x;
    const int wid  = tid >> 5;
    const int lane = tid & 31;
    const int wm   = (wid & 1) * 64;     // warp M offset
    const int wn   = (wid >> 1) * 32;    // warp N offset

    const int lrow = lane & 15;
    const int lcol = (lane >> 4) * 8;

    float acc[4][4][4];
    #pragma unroll
    for (int i = 0; i < 4; i++)
        #pragma unroll
        for (int j = 0; j < 4; j++)
            #pragma unroll
            for (int r = 0; r < 4; r++) acc[i][j][r] = 0.0f;

    const int nch = K / BKC;

    // prologue: chunk 0 -> buffer 0
    load_tile_cp(Ahi, Alo, bm, lda, 0, sA[0], tid);
    load_tile_cp(Bhi, Blo, bn, ldb, 0, sB[0], tid);
    CP_COMMIT();

    for (int kc = 0; kc < nch; kc++) {
        const int cur = kc & 1;
        if (kc + 1 < nch) {
            const int k0 = (kc + 1) * BKC;
            load_tile_cp(Ahi, Alo, bm, lda, k0, sA[cur ^ 1], tid);
            load_tile_cp(Bhi, Blo, bn, ldb, k0, sB[cur ^ 1], tid);
        }
        CP_COMMIT();
        CP_WAIT1();
        __syncthreads();

        const uint32_t sa = sA[cur];
        const uint32_t sb = sB[cur];
        #pragma unroll
        for (int t = 0; t < 2; t++) {            // two k16 steps per chunk
            const int kcol = t * 16 + lcol;
            uint32_t aF[4][4];                   // A fragments (hi, then lo)
            uint32_t bH[2][4], bL[2][4];
            #pragma unroll
            for (int mt = 0; mt < 4; mt++)
                ldmatrix_x4(aF[mt],
                    sa + (uint32_t)((wm + mt * 16 + lrow) * LDP + kcol) * 2);
            #pragma unroll
            for (int nb = 0; nb < 2; nb++) {
                const uint32_t ra =
                    sb + (uint32_t)((wn + nb * 16 + lrow) * LDP) * 2;
                ldmatrix_x4(bH[nb], ra + (uint32_t)kcol * 2);
                ldmatrix_x4(bL[nb], ra + (uint32_t)(32 + kcol) * 2);
            }
            // hi*hi and hi*lo
            #pragma unroll
            for (int mt = 0; mt < 4; mt++)
                #pragma unroll
                for (int nt = 0; nt < 4; nt++) {
                    const int nb = nt >> 1, sel = nt & 1;
                    mma_bf16(acc[mt][nt], aF[mt], bH[nb][sel], bH[nb][sel + 2]);
                    mma_bf16(acc[mt][nt], aF[mt], bL[nb][sel], bL[nb][sel + 2]);
                }
            // overwrite A fragments with lo half, then lo*hi
            #pragma unroll
            for (int mt = 0; mt < 4; mt++)
                ldmatrix_x4(aF[mt],
                    sa + (uint32_t)((wm + mt * 16 + lrow) * LDP + 32 + kcol) * 2);
            #pragma unroll
            for (int mt = 0; mt < 4; mt++)
                #pragma unroll
                for (int nt = 0; nt < 4; nt++) {
                    const int nb = nt >> 1, sel = nt & 1;
                    mma_bf16(acc[mt][nt], aF[mt], bH[nb][sel], bH[nb][sel + 2]);
                }
        }
        __syncthreads();
    }

    // ---- epilogue: reg r of frag (mt,nt) -> row wm+mt*16+(lane>>2)+8*(r>>1),
    //                                         col wn+nt*8+(lane&3)*2+(r&1)
    const int er = lane >> 2;
    const int ec = (lane & 3) * 2;
    #pragma unroll
    for (int mt = 0; mt < 4; mt++) {
        #pragma unroll
        for (int half = 0; half < 2; half++) {
            const int row = bm + wm + mt * 16 + er + half * 8;
            #pragma unroll
            for (int nt = 0; nt < 4; nt++) {
                const int col = bn + wn + nt * 8 + ec;
                float f0 = acc[mt][nt][half * 2 + 0] * alpha;
                float f1 = acc[mt][nt][half * 2 + 1] * alpha;
                if (BIAS) {
                    f0 += __ldg(&bias[col]);
                    f1 += __ldg(&bias[col + 1]);
                }
                if (OUT_MODE == 0) {
                    *reinterpret_cast<float2*>(Cf + (size_t)row * ldc + col) =
                        make_float2(f0, f1);
                } else if (OUT_MODE == 1) {
                    bf16 h0 = __float2bfloat16(f0);
                    bf16 h1 = __float2bfloat16(f1);
                    bf16 l0 = __float2bfloat16(f0 - __bfloat162float(h0));
                    bf16 l1 = __float2bfloat16(f1 - __bfloat162float(h1));
                    *reinterpret_cast<__nv_bfloat162*>(
                        Chi + (size_t)row * ldc + col) = __nv_bfloat162(h0, h1);
                    *reinterpret_cast<__nv_bfloat162*>(
                        Clo + (size_t)row * ldc + col) = __nv_bfloat162(l0, l1);
                } else {  // transposed store (V^T)
                    bf16 h0 = __float2bfloat16(f0);
                    bf16 h1 = __float2bfloat16(f1);
                    bf16 l0 = __float2bfloat16(f0 - __bfloat162float(h0));
                    bf16 l1 = __float2bfloat16(f1 - __bfloat162float(h1));
                    size_t o0 = (size_t)col * ldc + row;
                    size_t o1 = (size_t)(col + 1) * ldc + row;
                    Chi[o0] = h0;  Clo[o0] = l0;
                    Chi[o1] = h1;  Clo[o1] = l1;
                }
            }
        }
    }
}

// ---------------------------------------------------------------------------
__global__ __launch_bounds__(256)
void split_kernel(const float* __restrict__ x, bf16* __restrict__ hi,
                  bf16* __restrict__ lo, int n4)
{
    int i = blockIdx.x * 256 + threadIdx.x;
    if (i >= n4) return;
    float4 v = reinterpret_cast<const float4*>(x)[i];
    bf16 h0 = __float2bfloat16(v.x), h1 = __float2bfloat16(v.y);
    bf16 h2 = __float2bfloat16(v.z), h3 = __float2bfloat16(v.w);
    bf16 l0 = __float2bfloat16(v.x - __bfloat162float(h0));
    bf16 l1 = __float2bfloat16(v.y - __bfloat162float(h1));
    bf16 l2 = __float2bfloat16(v.z - __bfloat162float(h2));
    bf16 l3 = __float2bfloat16(v.w - __bfloat162float(h3));
    reinterpret_cast<__nv_bfloat162*>(hi)[i * 2]     = __nv_bfloat162(h0, h1);
    reinterpret_cast<__nv_bfloat162*>(hi)[i * 2 + 1] = __nv_bfloat162(h2, h3);
    reinterpret_cast<__nv_bfloat162*>(lo)[i * 2]     = __nv_bfloat162(l0, l1);
    reinterpret_cast<__nv_bfloat162*>(lo)[i * 2 + 1] = __nv_bfloat162(l2, l3);
}

// W [C,C] row-major -> WT hi/lo (WT[n][k] = W[k][n])
__global__ __launch_bounds__(256)
void tsplit_kernel(const float* __restrict__ W, bf16* __restrict__ hi,
                   bf16* __restrict__ lo)
{
    int idx = blockIdx.x * 256 + threadIdx.x;
    int n = idx >> 9, k = idx & 511;
    float x = __ldg(&W[k * Cv + n]);
    bf16 h = __float2bfloat16(x);
    hi[idx] = h;
    lo[idx] = __float2bfloat16(x - __bfloat162float(h));
}

// softmax over L=2048 (fp32 in) -> hi/lo bf16 out
__global__ __launch_bounds__(256)
void softmax_split_kernel(const float* __restrict__ att,
                          bf16* __restrict__ ahi, bf16* __restrict__ alo)
{
    const size_t base = (size_t)blockIdx.x * Lv;
    const float* p = att + base;
    const int tid = threadIdx.x, lane = tid & 31, warp = tid >> 5;
    __shared__ float red[8];

    float v[8];
    float m = -1e30f;
    #pragma unroll
    for (int i = 0; i < 8; i++) { v[i] = p[i * 256 + tid]; m = fmaxf(m, v[i]); }
    #pragma unroll
    for (int o = 16; o > 0; o >>= 1) m = fmaxf(m, __shfl_xor_sync(~0u, m, o));
    if (lane == 0) red[warp] = m;
    __syncthreads();
    m = red[0];
    #pragma unroll
    for (int i = 1; i < 8; i++) m = fmaxf(m, red[i]);
    __syncthreads();

    float s = 0.0f;
    #pragma unroll
    for (int i = 0; i < 8; i++) { v[i] = expf(v[i] - m); s += v[i]; }
    #pragma unroll
    for (int o = 16; o > 0; o >>= 1) s += __shfl_xor_sync(~0u, s, o);
    if (lane == 0) red[warp] = s;
    __syncthreads();
    s = red[0];
    #pragma unroll
    for (int i = 1; i < 8; i++) s += red[i];

    float inv = 1.0f / s;
    #pragma unroll
    for (int i = 0; i < 8; i++) {
        float w = v[i] * inv;
        bf16 h = __float2bfloat16(w);
        ahi[base + i * 256 + tid] = h;
        alo[base + i * 256 + tid] = __float2bfloat16(w - __bfloat162float(h));
    }
}

// ---------------------------------------------------------------------------
extern "C" void kernel_launch(void* const* d_in, const int* in_sizes, int n_in,
                              void* d_out, int out_size)
{
    const float* query = (const float*)d_in[0];
    const float* key   = (const float*)d_in[1];
    const float* value = (const float*)d_in[2];
    const float* Wq    = (const float*)d_in[3];
    const float* bq    = (const float*)d_in[4];
    const float* Wk    = (const float*)d_in[5];
    const float* bk    = (const float*)d_in[6];
    const float* Wv    = (const float*)d_in[7];
    const float* bv    = (const float*)d_in[8];
    const float* Wo    = (const float*)d_in[9];
    const float* bo    = (const float*)d_in[10];
    float* out = (float*)d_out;

    #define SYM(T, v, s) T* v; { void* _p; cudaGetSymbolAddress(&_p, s); v = (T*)_p; }
    SYM(bf16, xq_hi, g_xq_hi)  SYM(bf16, xq_lo, g_xq_lo)
    SYM(bf16, xk_hi, g_xk_hi)  SYM(bf16, xk_lo, g_xk_lo)
    SYM(bf16, xv_hi, g_xv_hi)  SYM(bf16, xv_lo, g_xv_lo)
    SYM(bf16, wqt_hi, g_wqt_hi) SYM(bf16, wqt_lo, g_wqt_lo)
    SYM(bf16, wkt_hi, g_wkt_hi) SYM(bf16, wkt_lo, g_wkt_lo)
    SYM(bf16, wvt_hi, g_wvt_hi) SYM(bf16, wvt_lo, g_wvt_lo)
    SYM(bf16, wot_hi, g_wot_hi) SYM(bf16, wot_lo, g_wot_lo)
    SYM(bf16, q_hi, g_q_hi)    SYM(bf16, q_lo, g_q_lo)
    SYM(bf16, k_hi, g_k_hi)    SYM(bf16, k_lo, g_k_lo)
    SYM(bf16, vt_hi, g_vt_hi)  SYM(bf16, vt_lo, g_vt_lo)
    SYM(float, att, g_att)
    SYM(bf16, att_hi, g_att_hi) SYM(bf16, att_lo, g_att_lo)
    SYM(bf16, ctx_hi, g_ctx_hi) SYM(bf16, ctx_lo, g_ctx_lo)
    #undef SYM

    // opt-in to 72KB dynamic smem for every instantiation (idempotent)
    static int attr_done = 0;
    if (!attr_done) {
        cudaFuncSetAttribute(mma_gemm<0, false>,
            cudaFuncAttributeMaxDynamicSharedMemorySize, SMEM_BYTES);
        cudaFuncSetAttribute(mma_gemm<0, true>,
            cudaFuncAttributeMaxDynamicSharedMemorySize, SMEM_BYTES);
        cudaFuncSetAttribute(mma_gemm<1, false>,
            cudaFuncAttributeMaxDynamicSharedMemorySize, SMEM_BYTES);
        cudaFuncSetAttribute(mma_gemm<1, true>,
            cudaFuncAttributeMaxDynamicSharedMemorySize, SMEM_BYTES);
        cudaFuncSetAttribute(mma_gemm<2, true>,
            cudaFuncAttributeMaxDynamicSharedMemorySize, SMEM_BYTES);
        attr_done = 1;
    }

    const float scale = 1.0f / sqrtf((float)Cv);
    const int n4 = Mfull * Cv / 4;
    dim3 blk(256);

    // 0) split inputs and weights to bf16 hi/lo
    split_kernel<<<n4 / 256, blk>>>(query, xq_hi, xq_lo, n4);
    split_kernel<<<n4 / 256, blk>>>(key,   xk_hi, xk_lo, n4);
    split_kernel<<<n4 / 256, blk>>>(value, xv_hi, xv_lo, n4);
    tsplit_kernel<<<Cv * Cv / 256, blk>>>(Wq, wqt_hi, wqt_lo);
    tsplit_kernel<<<Cv * Cv / 256, blk>>>(Wk, wkt_hi, wkt_lo);
    tsplit_kernel<<<Cv * Cv / 256, blk>>>(Wv, wvt_hi, wvt_lo);
    tsplit_kernel<<<Cv * Cv / 256, blk>>>(Wo, wot_hi, wot_lo);

    const long sIO  = (long)Lv * Cv;
    const long sAtt = (long)Lv * Lv;

    // 1) projections (weights strB = 0)
    dim3 gproj(Cv / 128, Lv / 128, Bv);  // (4,16,4)
    mma_gemm<1, true><<<gproj, blk, SMEM_BYTES>>>(xq_hi, xq_lo, wqt_hi, wqt_lo,
        bq, nullptr, q_hi, q_lo, Cv, Cv, Cv, Cv, sIO, 0, sIO, 1.0f);
    mma_gemm<1, true><<<gproj, blk, SMEM_BYTES>>>(xk_hi, xk_lo, wkt_hi, wkt_lo,
        bk, nullptr, k_hi, k_lo, Cv, Cv, Cv, Cv, sIO, 0, sIO, 1.0f);
    // V projection writes V^T [C, L] per batch (ldc = L)
    mma_gemm<2, true><<<gproj, blk, SMEM_BYTES>>>(xv_hi, xv_lo, wvt_hi, wvt_lo,
        bv, nullptr, vt_hi, vt_lo, Cv, Cv, Cv, Lv, sIO, 0, sIO, 1.0f);

    // 2) scores: att[b] = scale * q[b] @ k[b]^T (fp32 out)
    dim3 gsc(Lv / 128, Lv / 128, Bv);    // (16,16,4)
    mma_gemm<0, false><<<gsc, blk, SMEM_BYTES>>>(q_hi, q_lo, k_hi, k_lo,
        nullptr, att, nullptr, nullptr, Cv, Cv, Cv, Lv, sIO, sIO, sAtt, scale);

    // 3) softmax + bf16 split
    softmax_split_kernel<<<Mfull, blk>>>(att, att_hi, att_lo);

    // 4) ctx[b] = att[b] @ v[b]  (B = V^T, K-major)
    dim3 gav(Cv / 128, Lv / 128, Bv);    // (4,16,4)
    mma_gemm<1, false><<<gav, blk, SMEM_BYTES>>>(att_hi, att_lo, vt_hi, vt_lo,
        nullptr, nullptr, ctx_hi, ctx_lo, Lv, Lv, Lv, Cv, sAtt, sIO, sIO, 1.0f);

    // 5) out = ctx @ Wo + bo (fp32 to d_out)
    mma_gemm<0, true><<<gproj, blk, SMEM_BYTES>>>(ctx_hi, ctx_lo, wot_hi, wot_lo,
        bo, out, nullptr, nullptr, Cv, Cv, Cv, Cv, sIO, 0, sIO, 1.0f);
}